// round 14
// baseline (speedup 1.0000x reference)
#include <cuda_runtime.h>

typedef unsigned long long u64;

__device__ __forceinline__ u64 pk2(float lo, float hi) {
    u64 r; asm("mov.b64 %0,{%1,%2};" : "=l"(r) : "f"(lo), "f"(hi)); return r;
}
__device__ __forceinline__ u64 fma2(u64 a, u64 b, u64 c) {
    u64 d; asm("fma.rn.f32x2 %0,%1,%2,%3;" : "=l"(d) : "l"(a), "l"(b), "l"(c)); return d;
}
__device__ __forceinline__ float sum2(u64 a) {
    float lo, hi; asm("mov.b64 {%0,%1},%2;" : "=f"(lo), "=f"(hi) : "l"(a)); return lo + hi;
}
__device__ __forceinline__ unsigned smem_u32(const void* p) {
    unsigned a;
    asm("{ .reg .u64 t; cvta.to.shared.u64 t, %1; cvt.u32.u64 %0, t; }" : "=r"(a) : "l"(p));
    return a;
}
__device__ __forceinline__ void cp_async16(unsigned s, const void* g) {
    asm volatile("cp.async.cg.shared.global [%0], [%1], 16;" :: "r"(s), "l"(g));
}

// Scratch
__device__ float g_n1[2048 * 8];     // n1[row][k]
__device__ float g_n2T[6 * 2048];    // n2 transposed [k][row]

// ---------------------------------------------------------------------------
// k_gcn: register-blocked. 128 blocks x 256 threads.
// Block tile: 16 rows x 128 d. Thread tile: 4 rows x 2 d.
// Inner step everywhere: 1 bcast LDS.128 (4 rows) + 1 LDS.64 (2 d) + 4 fma2.
//   Phase A: t = mean_h(wa) @ x         (j in 8 chunks of 32)
//   Phase B: gcn = relu(t @ Ww^T + b)   (k in 4 chunks of 32, w transposed)
//   Phase C: out = gcn @ Wxx^T + b
//   Phase D: n1/n2 (192 dots)
// smem: pool1 = x_s[32][128]+a_s[32][20] overlaid with w_s[32][130];
//       tg    = t_sT[128][20] overwritten by g_sT[128][20].
// ---------------------------------------------------------------------------
__global__ void __launch_bounds__(256) k_gcn(const float* __restrict__ x,
                                             const float* __restrict__ wa,
                                             const float* __restrict__ Ww,
                                             const float* __restrict__ Wb,
                                             const float* __restrict__ Wx_w,
                                             const float* __restrict__ Wxx,
                                             const float* __restrict__ Wxxb,
                                             float* __restrict__ out) {
    __shared__ __align__(16) float pool1[4736];   // x_s(4096)+a_s(640) | w_s(4160)
    __shared__ __align__(16) float tg[2560];      // t_sT then g_sT: [d/k][20]

    int tid = threadIdx.x;
    int tc  = tid & 63;        // d-pair: d = 2tc, 2tc+1
    int tr  = tid >> 6;        // row group: rows 4tr..4tr+3 (uniform per warp)
    int b   = blockIdx.x >> 4;
    int i0  = (blockIdx.x & 15) << 4;
    int r0  = blockIdx.x << 4;
    float* x_s = pool1;            // [32][128]
    float* a_s = pool1 + 4096;     // [32][20]  (a_s[jj][row])
    float* w_s = pool1;            // [32][130] (w_s[kk][d])
    const float inv6 = 1.0f / 6.0f;

    float4 acc4[2];
    acc4[0] = make_float4(0.f, 0.f, 0.f, 0.f);
    acc4[1] = acc4[0];

    // ================= Phase A: t = mean_h(wa) @ x =================
    for (int c = 0; c < 8; c++) {
        int j0 = c * 32;
        // stage x[b][j0..j0+31][:]  (16KB, coalesced float4)
        const float4* xs = (const float4*)(x + ((long)(b * 256 + j0)) * 128);
        float4*       xd = (float4*)x_s;
        #pragma unroll
        for (int p = 0; p < 4; p++) xd[tid + p * 256] = xs[tid + p * 256];
        // stage a_s[jj][row] = mean_h wa[b,h,i0+row,j0+jj]
        #pragma unroll
        for (int p = 0; p < 2; p++) {
            int jj = tid & 31, row = (tid >> 5) + p * 8;
            float s = 0.0f;
            #pragma unroll
            for (int h = 0; h < 6; h++)
                s += wa[((long)(b * 6 + h) * 256 + i0 + row) * 256 + j0 + jj];
            a_s[jj * 20 + row] = s * inv6;
        }
        __syncthreads();
        #pragma unroll
        for (int jj = 0; jj < 32; jj++) {
            float4 av = *(const float4*)&a_s[jj * 20 + 4 * tr];   // bcast, 1 wf
            float2 xv = *(const float2*)&x_s[jj * 128 + 2 * tc];  // 2 wf
            u64 x0 = pk2(xv.x, xv.x), x1 = pk2(xv.y, xv.y);
            *(u64*)&acc4[0].x = fma2(*(const u64*)&av.x, x0, *(u64*)&acc4[0].x);
            *(u64*)&acc4[0].z = fma2(*(const u64*)&av.z, x0, *(u64*)&acc4[0].z);
            *(u64*)&acc4[1].x = fma2(*(const u64*)&av.x, x1, *(u64*)&acc4[1].x);
            *(u64*)&acc4[1].z = fma2(*(const u64*)&av.z, x1, *(u64*)&acc4[1].z);
        }
        __syncthreads();
    }
    // store t transposed: tg[d][4 rows] (float4, conflict-light, once)
    #pragma unroll
    for (int q = 0; q < 2; q++)
        *(float4*)&tg[(2 * tc + q) * 20 + 4 * tr] = acc4[q];
    __syncthreads();

    // ================= Phase B: gcn = relu(t @ Ww^T + b) =================
    acc4[0] = make_float4(0.f, 0.f, 0.f, 0.f);
    acc4[1] = acc4[0];
    for (int kt = 0; kt < 4; kt++) {
        int k0 = kt * 32;
        #pragma unroll
        for (int p = 0; p < 16; p++) {          // stage w_s[kk][d] = Ww[d][k0+kk]
            int idx = tid + p * 256;
            int kk = idx & 31, d = idx >> 5;
            w_s[kk * 130 + d] = Ww[d * 128 + k0 + kk];
        }
        __syncthreads();
        #pragma unroll
        for (int kk = 0; kk < 32; kk++) {
            float4 tv = *(const float4*)&tg[(k0 + kk) * 20 + 4 * tr];   // bcast
            float2 wv = *(const float2*)&w_s[kk * 130 + 2 * tc];        // 2 wf
            u64 w0 = pk2(wv.x, wv.x), w1 = pk2(wv.y, wv.y);
            *(u64*)&acc4[0].x = fma2(*(const u64*)&tv.x, w0, *(u64*)&acc4[0].x);
            *(u64*)&acc4[0].z = fma2(*(const u64*)&tv.z, w0, *(u64*)&acc4[0].z);
            *(u64*)&acc4[1].x = fma2(*(const u64*)&tv.x, w1, *(u64*)&acc4[1].x);
            *(u64*)&acc4[1].z = fma2(*(const u64*)&tv.z, w1, *(u64*)&acc4[1].z);
        }
        __syncthreads();
    }
    {   // relu + bias; overwrite tg with g (t is dead)
        float b0 = Wb[2 * tc], b1 = Wb[2 * tc + 1];
        acc4[0].x = fmaxf(acc4[0].x + b0, 0.f);
        acc4[0].y = fmaxf(acc4[0].y + b0, 0.f);
        acc4[0].z = fmaxf(acc4[0].z + b0, 0.f);
        acc4[0].w = fmaxf(acc4[0].w + b0, 0.f);
        acc4[1].x = fmaxf(acc4[1].x + b1, 0.f);
        acc4[1].y = fmaxf(acc4[1].y + b1, 0.f);
        acc4[1].z = fmaxf(acc4[1].z + b1, 0.f);
        acc4[1].w = fmaxf(acc4[1].w + b1, 0.f);
    }
    #pragma unroll
    for (int q = 0; q < 2; q++)
        *(float4*)&tg[(2 * tc + q) * 20 + 4 * tr] = acc4[q];
    __syncthreads();

    // ================= Phase C: out = gcn @ Wxx^T + b =================
    acc4[0] = make_float4(0.f, 0.f, 0.f, 0.f);
    acc4[1] = acc4[0];
    for (int kt = 0; kt < 4; kt++) {
        int k0 = kt * 32;
        #pragma unroll
        for (int p = 0; p < 16; p++) {
            int idx = tid + p * 256;
            int kk = idx & 31, d = idx >> 5;
            w_s[kk * 130 + d] = Wxx[d * 128 + k0 + kk];
        }
        __syncthreads();
        #pragma unroll
        for (int kk = 0; kk < 32; kk++) {
            float4 gv = *(const float4*)&tg[(k0 + kk) * 20 + 4 * tr];
            float2 wv = *(const float2*)&w_s[kk * 130 + 2 * tc];
            u64 w0 = pk2(wv.x, wv.x), w1 = pk2(wv.y, wv.y);
            *(u64*)&acc4[0].x = fma2(*(const u64*)&gv.x, w0, *(u64*)&acc4[0].x);
            *(u64*)&acc4[0].z = fma2(*(const u64*)&gv.z, w0, *(u64*)&acc4[0].z);
            *(u64*)&acc4[1].x = fma2(*(const u64*)&gv.x, w1, *(u64*)&acc4[1].x);
            *(u64*)&acc4[1].z = fma2(*(const u64*)&gv.z, w1, *(u64*)&acc4[1].z);
        }
        __syncthreads();
    }
    {
        float b0 = Wxxb[2 * tc], b1 = Wxxb[2 * tc + 1];
        #pragma unroll
        for (int s = 0; s < 4; s++) {
            out[(long)(r0 + 4 * tr + s) * 128 + 2 * tc]     = ((float*)&acc4[0])[s] + b0;
            out[(long)(r0 + 4 * tr + s) * 128 + 2 * tc + 1] = ((float*)&acc4[1])[s] + b1;
        }
    }

    // ================= Phase D: n1/n2 — 192 dots of length 128 =================
    if (tid < 192) {
        int sel = tid >= 96;               // 0 -> n1, 1 -> n2
        int q   = tid - sel * 96;
        int row = q / 6, k = q % 6;        // row 0..15
        const float* w = Wx_w + k * 294 + 6 + sel * 128;
        float s = 0.0f;
        #pragma unroll 4
        for (int dd = 0; dd < 128; dd++)
            s += tg[dd * 20 + row] * __ldg(&w[dd]);
        if (sel == 0) g_n1[(r0 + row) * 8 + k]     = s;
        else          g_n2T[k * 2048 + r0 + row]   = s;
    }
}

// ---------------------------------------------------------------------------
// k_adj (r6-proven body, plain serial): wa-term + e-term computed from smem,
// n1/n2 folded directly (k_gcn complete by stream order).
// ---------------------------------------------------------------------------
__global__ void __launch_bounds__(256, 6) k_adj(const float* __restrict__ wa,
                                                const float* __restrict__ e,
                                                const float* __restrict__ Wx_w,
                                                const float* __restrict__ Wx_b,
                                                float* __restrict__ adj_out) {
    __shared__ __align__(16) float e_s[256 * 36];
    __shared__ __align__(16) float Wa_s[40];
    __shared__ __align__(16) float We_s[200];
    __shared__ __align__(16) float n1b_s[16];
    int b   = blockIdx.x >> 8;
    int i   = blockIdx.x & 255;
    int tid = threadIdx.x;

    const float4* e4 = (const float4*)(e + (((long)b * 256 + i) * 256) * 32);
    #pragma unroll
    for (int it = 0; it < 8; it++) {
        int idx = tid + it * 256;
        unsigned dst = smem_u32(&e_s[(idx >> 3) * 36 + (idx & 7) * 4]);
        cp_async16(dst, &e4[idx]);
    }
    asm volatile("cp.async.commit_group;" ::: "memory");

    float wv[6];
    #pragma unroll
    for (int h = 0; h < 6; h++)
        wv[h] = wa[(((long)(b * 6 + h) * 256) + i) * 256 + tid];
    if (tid < 36) Wa_s[tid] = Wx_w[(tid / 6) * 294 + tid % 6];
    if (tid >= 64 && tid < 256) {
        int t = tid - 64;
        We_s[t] = Wx_w[(t >> 5) * 294 + 262 + (t & 31)];
    }
    if (tid >= 48 && tid < 54) n1b_s[8 + tid - 48] = Wx_b[tid - 48];
    if (tid < 6) n1b_s[tid] = g_n1[((long)b * 256 + i) * 8 + tid];
    float n2v[6];
    #pragma unroll
    for (int k = 0; k < 6; k++) n2v[k] = g_n2T[k * 2048 + b * 256 + tid];

    asm volatile("cp.async.wait_group 0;" ::: "memory");
    __syncthreads();

    u64 acc2[6];
    #pragma unroll
    for (int k = 0; k < 6; k++) acc2[k] = 0ull;

    u64 wp0 = pk2(wv[0], wv[1]), wp1 = pk2(wv[2], wv[3]), wp2 = pk2(wv[4], wv[5]);
    #pragma unroll
    for (int k = 0; k < 6; k++) {
        acc2[k] = fma2(*(const u64*)&Wa_s[k * 6 + 0], wp0, acc2[k]);
        acc2[k] = fma2(*(const u64*)&Wa_s[k * 6 + 2], wp1, acc2[k]);
        acc2[k] = fma2(*(const u64*)&Wa_s[k * 6 + 4], wp2, acc2[k]);
    }

    const float4* ep = (const float4*)&e_s[tid * 36];
    #pragma unroll
    for (int q = 0; q < 8; q++) {
        float4 w = ep[q];
        u64 ev0 = pk2(w.x, w.y);
        u64 ev1 = pk2(w.z, w.w);
        #pragma unroll
        for (int k = 0; k < 6; k++) {
            acc2[k] = fma2(ev0, *(const u64*)&We_s[k * 32 + q * 4 + 0], acc2[k]);
            acc2[k] = fma2(ev1, *(const u64*)&We_s[k * 32 + q * 4 + 2], acc2[k]);
        }
    }

    long ob = ((long)(b * 6) * 65536) + (long)i * 256 + tid;
    #pragma unroll
    for (int k = 0; k < 6; k++)
        adj_out[ob + (long)k * 65536] = sum2(acc2[k]) + n1b_s[k] + n1b_s[8 + k] + n2v[k];
}

// ---------------------------------------------------------------------------
extern "C" void kernel_launch(void* const* d_in, const int* in_sizes, int n_in,
                              void* d_out, int out_size) {
    const float* x     = (const float*)d_in[0];
    const float* wa    = (const float*)d_in[1];
    const float* e     = (const float*)d_in[2];
    const float* W_w   = (const float*)d_in[3];
    const float* W_b   = (const float*)d_in[4];
    const float* Wx_w  = (const float*)d_in[5];
    const float* Wx_b  = (const float*)d_in[6];
    const float* Wxx_w = (const float*)d_in[7];
    const float* Wxx_b = (const float*)d_in[8];

    float* out     = (float*)d_out;            // (B,L,D)
    float* adj_out = out + 8 * 256 * 128;      // (B,H,L,L)

    k_gcn<<<128, 256>>>(x, wa, W_w, W_b, Wx_w, Wxx_w, Wxx_b, out);
    k_adj<<<2048, 256>>>(wa, e, Wx_w, Wx_b, adj_out);
}

// round 15
// speedup vs baseline: 1.0061x; 1.0061x over previous
#include <cuda_runtime.h>

typedef unsigned long long u64;

__device__ __forceinline__ u64 pk2(float lo, float hi) {
    u64 r; asm("mov.b64 %0,{%1,%2};" : "=l"(r) : "f"(lo), "f"(hi)); return r;
}
__device__ __forceinline__ u64 fma2(u64 a, u64 b, u64 c) {
    u64 d; asm("fma.rn.f32x2 %0,%1,%2,%3;" : "=l"(d) : "l"(a), "l"(b), "l"(c)); return d;
}
__device__ __forceinline__ float sum2(u64 a) {
    float lo, hi; asm("mov.b64 {%0,%1},%2;" : "=f"(lo), "=f"(hi) : "l"(a)); return lo + hi;
}
__device__ __forceinline__ unsigned smem_u32(const void* p) {
    unsigned a;
    asm("{ .reg .u64 t; cvta.to.shared.u64 t, %1; cvt.u32.u64 %0, t; }" : "=r"(a) : "l"(p));
    return a;
}
__device__ __forceinline__ void cp_async16(unsigned s, const void* g) {
    asm volatile("cp.async.cg.shared.global [%0], [%1], 16;" :: "r"(s), "l"(g));
}

// Scratch (no flags, no inter-block waits anywhere)
__device__ float g_n1[2048 * 8];     // n1[row][k]
__device__ float g_n2T[6 * 2048];    // n2 transposed [k][row]

// ---------------------------------------------------------------------------
// Fused kernel:
//   blocks 0..127    = GCN role: register-blocked (r14 body, 14K wf/block)
//                      16 rows x 128 d tile, thread-tile 4 rows x 2 d
//   blocks 128..2175 = ADJ role: wa-term + e-term + bias -> adj_out PARTIAL
// gcn ids lowest -> 1 gcn block/SM from wave 1, latency-bound with low pipe
// use; adj blocks fill the remaining 4 slots/SM and stream DRAM around them.
// ---------------------------------------------------------------------------
__global__ void __launch_bounds__(256, 5) k_fused(const float* __restrict__ x,
                                                  const float* __restrict__ wa,
                                                  const float* __restrict__ e,
                                                  const float* __restrict__ Ww,
                                                  const float* __restrict__ Wb,
                                                  const float* __restrict__ Wx_w,
                                                  const float* __restrict__ Wx_b,
                                                  const float* __restrict__ Wxx,
                                                  const float* __restrict__ Wxxb,
                                                  float* __restrict__ out,
                                                  float* __restrict__ adj_out) {
    __shared__ __align__(16) float smem[9728];    // 38KB union of both roles
    int tid = threadIdx.x;

    if (blockIdx.x < 128) {
        // ==================== GCN role (register-blocked) ====================
        float* pool1 = smem;            // x_s(4096)+a_s(640) | w_s(4160)
        float* tg    = smem + 4736;     // t_sT then g_sT: [d/k][20]
        int tc  = tid & 63;        // d-pair: d = 2tc, 2tc+1
        int tr  = tid >> 6;        // row group: rows 4tr..4tr+3
        int b   = blockIdx.x >> 4;
        int i0  = (blockIdx.x & 15) << 4;
        int r0  = blockIdx.x << 4;
        float* x_s = pool1;            // [32][128]
        float* a_s = pool1 + 4096;     // [32][20]
        float* w_s = pool1;            // [32][130]
        const float inv6 = 1.0f / 6.0f;

        float4 acc4[2];
        acc4[0] = make_float4(0.f, 0.f, 0.f, 0.f);
        acc4[1] = acc4[0];

        // ---- Phase A: t = mean_h(wa) @ x ----
        for (int c = 0; c < 8; c++) {
            int j0 = c * 32;
            const float4* xs = (const float4*)(x + ((long)(b * 256 + j0)) * 128);
            float4*       xd = (float4*)x_s;
            #pragma unroll
            for (int p = 0; p < 4; p++) xd[tid + p * 256] = xs[tid + p * 256];
            #pragma unroll
            for (int p = 0; p < 2; p++) {
                int jj = tid & 31, row = (tid >> 5) + p * 8;
                float s = 0.0f;
                #pragma unroll
                for (int h = 0; h < 6; h++)
                    s += wa[((long)(b * 6 + h) * 256 + i0 + row) * 256 + j0 + jj];
                a_s[jj * 20 + row] = s * inv6;
            }
            __syncthreads();
            #pragma unroll
            for (int jj = 0; jj < 32; jj++) {
                float4 av = *(const float4*)&a_s[jj * 20 + 4 * tr];   // bcast
                float2 xv = *(const float2*)&x_s[jj * 128 + 2 * tc];
                u64 x0 = pk2(xv.x, xv.x), x1 = pk2(xv.y, xv.y);
                *(u64*)&acc4[0].x = fma2(*(const u64*)&av.x, x0, *(u64*)&acc4[0].x);
                *(u64*)&acc4[0].z = fma2(*(const u64*)&av.z, x0, *(u64*)&acc4[0].z);
                *(u64*)&acc4[1].x = fma2(*(const u64*)&av.x, x1, *(u64*)&acc4[1].x);
                *(u64*)&acc4[1].z = fma2(*(const u64*)&av.z, x1, *(u64*)&acc4[1].z);
            }
            __syncthreads();
        }
        #pragma unroll
        for (int q = 0; q < 2; q++)
            *(float4*)&tg[(2 * tc + q) * 20 + 4 * tr] = acc4[q];
        __syncthreads();

        // ---- Phase B: gcn = relu(t @ Ww^T + b) ----
        acc4[0] = make_float4(0.f, 0.f, 0.f, 0.f);
        acc4[1] = acc4[0];
        for (int kt = 0; kt < 4; kt++) {
            int k0 = kt * 32;
            #pragma unroll
            for (int p = 0; p < 16; p++) {
                int idx = tid + p * 256;
                int kk = idx & 31, d = idx >> 5;
                w_s[kk * 130 + d] = Ww[d * 128 + k0 + kk];
            }
            __syncthreads();
            #pragma unroll
            for (int kk = 0; kk < 32; kk++) {
                float4 tv = *(const float4*)&tg[(k0 + kk) * 20 + 4 * tr];
                float2 wv = *(const float2*)&w_s[kk * 130 + 2 * tc];
                u64 w0 = pk2(wv.x, wv.x), w1 = pk2(wv.y, wv.y);
                *(u64*)&acc4[0].x = fma2(*(const u64*)&tv.x, w0, *(u64*)&acc4[0].x);
                *(u64*)&acc4[0].z = fma2(*(const u64*)&tv.z, w0, *(u64*)&acc4[0].z);
                *(u64*)&acc4[1].x = fma2(*(const u64*)&tv.x, w1, *(u64*)&acc4[1].x);
                *(u64*)&acc4[1].z = fma2(*(const u64*)&tv.z, w1, *(u64*)&acc4[1].z);
            }
            __syncthreads();
        }
        {
            float b0 = Wb[2 * tc], b1 = Wb[2 * tc + 1];
            acc4[0].x = fmaxf(acc4[0].x + b0, 0.f);
            acc4[0].y = fmaxf(acc4[0].y + b0, 0.f);
            acc4[0].z = fmaxf(acc4[0].z + b0, 0.f);
            acc4[0].w = fmaxf(acc4[0].w + b0, 0.f);
            acc4[1].x = fmaxf(acc4[1].x + b1, 0.f);
            acc4[1].y = fmaxf(acc4[1].y + b1, 0.f);
            acc4[1].z = fmaxf(acc4[1].z + b1, 0.f);
            acc4[1].w = fmaxf(acc4[1].w + b1, 0.f);
        }
        #pragma unroll
        for (int q = 0; q < 2; q++)
            *(float4*)&tg[(2 * tc + q) * 20 + 4 * tr] = acc4[q];
        __syncthreads();

        // ---- Phase C: out = gcn @ Wxx^T + b ----
        acc4[0] = make_float4(0.f, 0.f, 0.f, 0.f);
        acc4[1] = acc4[0];
        for (int kt = 0; kt < 4; kt++) {
            int k0 = kt * 32;
            #pragma unroll
            for (int p = 0; p < 16; p++) {
                int idx = tid + p * 256;
                int kk = idx & 31, d = idx >> 5;
                w_s[kk * 130 + d] = Wxx[d * 128 + k0 + kk];
            }
            __syncthreads();
            #pragma unroll
            for (int kk = 0; kk < 32; kk++) {
                float4 gv = *(const float4*)&tg[(k0 + kk) * 20 + 4 * tr];
                float2 wv = *(const float2*)&w_s[kk * 130 + 2 * tc];
                u64 w0 = pk2(wv.x, wv.x), w1 = pk2(wv.y, wv.y);
                *(u64*)&acc4[0].x = fma2(*(const u64*)&gv.x, w0, *(u64*)&acc4[0].x);
                *(u64*)&acc4[0].z = fma2(*(const u64*)&gv.z, w0, *(u64*)&acc4[0].z);
                *(u64*)&acc4[1].x = fma2(*(const u64*)&gv.x, w1, *(u64*)&acc4[1].x);
                *(u64*)&acc4[1].z = fma2(*(const u64*)&gv.z, w1, *(u64*)&acc4[1].z);
            }
            __syncthreads();
        }
        {
            float b0 = Wxxb[2 * tc], b1 = Wxxb[2 * tc + 1];
            #pragma unroll
            for (int s = 0; s < 4; s++) {
                out[(long)(r0 + 4 * tr + s) * 128 + 2 * tc]     = ((float*)&acc4[0])[s] + b0;
                out[(long)(r0 + 4 * tr + s) * 128 + 2 * tc + 1] = ((float*)&acc4[1])[s] + b1;
            }
        }

        // ---- Phase D: n1/n2 — 192 dots of length 128 ----
        if (tid < 192) {
            int sel = tid >= 96;
            int q   = tid - sel * 96;
            int row = q / 6, k = q % 6;
            const float* w = Wx_w + k * 294 + 6 + sel * 128;
            float s = 0.0f;
            #pragma unroll 4
            for (int dd = 0; dd < 128; dd++)
                s += tg[dd * 20 + row] * __ldg(&w[dd]);
            if (sel == 0) g_n1[(r0 + row) * 8 + k]   = s;
            else          g_n2T[k * 2048 + r0 + row] = s;
        }

    } else {
        // ==================== ADJ role (partial, no waits) ====================
        float* e_s    = smem;            // [j][36], 9216 floats
        float* Wa_s   = smem + 9216;     // 40
        float* We_s   = smem + 9280;     // 200
        float* bias_s = smem + 9480;     // 8
        int abid = blockIdx.x - 128;
        int b    = abid >> 8;
        int i    = abid & 255;

        const float4* e4 = (const float4*)(e + (((long)b * 256 + i) * 256) * 32);
        #pragma unroll
        for (int it = 0; it < 8; it++) {
            int idx = tid + it * 256;
            unsigned dst = smem_u32(&e_s[(idx >> 3) * 36 + (idx & 7) * 4]);
            cp_async16(dst, &e4[idx]);
        }
        asm volatile("cp.async.commit_group;" ::: "memory");

        float wv[6];
        #pragma unroll
        for (int h = 0; h < 6; h++)
            wv[h] = wa[(((long)(b * 6 + h) * 256) + i) * 256 + tid];
        if (tid < 36) Wa_s[tid] = Wx_w[(tid / 6) * 294 + tid % 6];
        if (tid >= 64 && tid < 256) {
            int t = tid - 64;
            We_s[t] = Wx_w[(t >> 5) * 294 + 262 + (t & 31)];
        }
        if (tid >= 48 && tid < 54) bias_s[tid - 48] = Wx_b[tid - 48];

        asm volatile("cp.async.wait_group 0;" ::: "memory");
        __syncthreads();

        u64 acc2[6];
        #pragma unroll
        for (int k = 0; k < 6; k++) acc2[k] = 0ull;

        u64 wp0 = pk2(wv[0], wv[1]), wp1 = pk2(wv[2], wv[3]), wp2 = pk2(wv[4], wv[5]);
        #pragma unroll
        for (int k = 0; k < 6; k++) {
            acc2[k] = fma2(*(const u64*)&Wa_s[k * 6 + 0], wp0, acc2[k]);
            acc2[k] = fma2(*(const u64*)&Wa_s[k * 6 + 2], wp1, acc2[k]);
            acc2[k] = fma2(*(const u64*)&Wa_s[k * 6 + 4], wp2, acc2[k]);
        }

        const float4* ep = (const float4*)&e_s[tid * 36];
        #pragma unroll
        for (int q = 0; q < 8; q++) {
            float4 w = ep[q];
            u64 ev0 = pk2(w.x, w.y);
            u64 ev1 = pk2(w.z, w.w);
            #pragma unroll
            for (int k = 0; k < 6; k++) {
                acc2[k] = fma2(ev0, *(const u64*)&We_s[k * 32 + q * 4 + 0], acc2[k]);
                acc2[k] = fma2(ev1, *(const u64*)&We_s[k * 32 + q * 4 + 2], acc2[k]);
            }
        }

        long ob = ((long)(b * 6) * 65536) + (long)i * 256 + tid;
        #pragma unroll
        for (int k = 0; k < 6; k++)
            adj_out[ob + (long)k * 65536] = sum2(acc2[k]) + bias_s[k];
    }
}

// ---------------------------------------------------------------------------
// adj_out[b,k,i,j] += n1[b,i,k] + n2[b,j,k]
// grid = 1536 blocks x 256 threads; block = (b,k, 8 i-rows); thread = 8 j.
// 2 independent float4 RMWs per thread for MLP.
// ---------------------------------------------------------------------------
__global__ void __launch_bounds__(256) k_add(float* __restrict__ adj_out) {
    int bid = blockIdx.x;
    int bk  = bid >> 5;               // b*6+k  (48 pairs x 32 blocks)
    int iq  = bid & 31;
    int b   = bk / 6, k = bk - b * 6;
    int tid = threadIdx.x;
    int ir  = tid >> 5;               // 0..7
    int jj  = (tid & 31) << 3;        // 8 j per thread
    int i   = iq * 8 + ir;

    float  n1v  = g_n1[((b * 256 + i) * 8) + k];
    float4 n2a  = *(const float4*)&g_n2T[k * 2048 + b * 256 + jj];
    float4 n2b  = *(const float4*)&g_n2T[k * 2048 + b * 256 + jj + 4];

    long off = ((long)(b * 6 + k) << 16) + i * 256 + jj;
    float4 v0 = *(float4*)&adj_out[off];
    float4 v1 = *(float4*)&adj_out[off + 4];
    v0.x += n1v + n2a.x;  v0.y += n1v + n2a.y;
    v0.z += n1v + n2a.z;  v0.w += n1v + n2a.w;
    v1.x += n1v + n2b.x;  v1.y += n1v + n2b.y;
    v1.z += n1v + n2b.z;  v1.w += n1v + n2b.w;
    *(float4*)&adj_out[off]     = v0;
    *(float4*)&adj_out[off + 4] = v1;
}

// ---------------------------------------------------------------------------
extern "C" void kernel_launch(void* const* d_in, const int* in_sizes, int n_in,
                              void* d_out, int out_size) {
    const float* x     = (const float*)d_in[0];
    const float* wa    = (const float*)d_in[1];
    const float* e     = (const float*)d_in[2];
    const float* W_w   = (const float*)d_in[3];
    const float* W_b   = (const float*)d_in[4];
    const float* Wx_w  = (const float*)d_in[5];
    const float* Wx_b  = (const float*)d_in[6];
    const float* Wxx_w = (const float*)d_in[7];
    const float* Wxx_b = (const float*)d_in[8];

    float* out     = (float*)d_out;            // (B,L,D)
    float* adj_out = out + 8 * 256 * 128;      // (B,H,L,L)

    k_fused<<<2176, 256>>>(x, wa, e, W_w, W_b, Wx_w, Wx_b, Wxx_w, Wxx_b,
                           out, adj_out);
    k_add<<<1536, 256>>>(adj_out);
}